// round 11
// baseline (speedup 1.0000x reference)
#include <cuda_runtime.h>
#include <cstdint>

#define NPTS    131072
#define NBOOK   4
#define KCODES  1024
#define NCODES  4096
#define THREADS 256
#define CHUNKS  64          // 64 codes per chunk

// smem byte offsets
#define SM_AHI  0           // 64KB  A-hi frags
#define SM_ALO  65536       // 64KB  A-lo frags
#define SM_B    131072      // 2 x 32KB raw B frags (double buffer)
#define SM_EX   196608      // 2KB   cross-warp exchange
#define SMEM_TOTAL (196608 + 2048)

__device__ float g_csq[NCODES];
__device__ float g_marg[NPTS * NBOOK];
__device__ int   g_sec[NPTS * NBOOK];

__device__ __forceinline__ float tf32r(float v) {
    uint32_t r; asm("cvt.rna.tf32.f32 %0, %1;" : "=r"(r) : "f"(v));
    return __uint_as_float(r);
}
__device__ __forceinline__ bool lless(float v, int i, float v2, int i2) {
    return v < v2 || (v == v2 && i < i2);
}
// keep (best, second) with lowest-index tie-break
__device__ __forceinline__ void upd(float& v1, int& i1, float& v2, int& i2,
                                    float s, int idx) {
    if (lless(s, idx, v1, i1)) { v2 = v1; i2 = i1; v1 = s; i1 = idx; }
    else if (lless(s, idx, v2, i2)) { v2 = s; i2 = idx; }
}
__device__ __forceinline__ void mrg(float& v1, int& i1, float& v2, int& i2,
                                    float ov1, int oi1, float ov2, int oi2) {
    if (lless(ov1, oi1, v1, i1)) {
        if (lless(v1, i1, ov2, oi2)) { v2 = v1; i2 = i1; }
        else { v2 = ov2; i2 = oi2; }
        v1 = ov1; i1 = oi1;
    } else if (lless(ov1, oi1, v2, i2)) { v2 = ov1; i2 = oi1; }
}
__device__ __forceinline__ void mma8(float* d, const uint32_t* a, const uint32_t* b) {
    asm volatile(
        "mma.sync.aligned.m16n8k8.row.col.f32.tf32.tf32.f32 "
        "{%0,%1,%2,%3}, {%4,%5,%6,%7}, {%8,%9}, {%0,%1,%2,%3};"
        : "+f"(d[0]), "+f"(d[1]), "+f"(d[2]), "+f"(d[3])
        : "r"(a[0]), "r"(a[1]), "r"(a[2]), "r"(a[3]), "r"(b[0]), "r"(b[1]));
}

// ||c||^2 for all 4096 codes. One warp per code.
__global__ void csq_kernel(const float* __restrict__ cb) {
    int warp = threadIdx.x >> 5, lane = threadIdx.x & 31;
    int code = blockIdx.x * 8 + warp;
    float4 v = reinterpret_cast<const float4*>(cb)[code * 32 + lane];
    float s = v.x * v.x + v.y * v.y + v.z * v.z + v.w * v.w;
#pragma unroll
    for (int o = 16; o > 0; o >>= 1) s += __shfl_xor_sync(0xffffffffu, s, o);
    if (lane == 0) g_csq[code] = s;
}

extern __shared__ char smem[];

__global__ void __launch_bounds__(THREADS, 1)
rqk_mma(const float* __restrict__ x, const float* __restrict__ cb,
        float* __restrict__ out) {
    const int tid  = threadIdx.x;
    const int lane = tid & 31;
    const int warp = tid >> 5;
    const int rr   = warp & 3;     // row group: rows rr*32 .. +31
    const int cc   = warp >> 2;    // code half: codes cc*32 .. +31 of chunk
    const int grp  = lane >> 2;
    const int th   = lane & 3;
    const int row0 = blockIdx.x * 128;

    float*  AH = reinterpret_cast<float*>(smem + SM_AHI);
    float*  AL = reinterpret_cast<float*>(smem + SM_ALO);
    float4* EX = reinterpret_cast<float4*>(smem + SM_EX);

    // ---- A setup: load x rows, split tf32 hi/lo, store fragment-major ----
    // frag slot of (row,k): tile=(row>>5)*2+((row>>4)&1), lane=(row&7)*4+(k&3),
    // slot=((k>>2)&1)*2+((row>>3)&1), ks=k>>3
    {
        const float4* x4 = reinterpret_cast<const float4*>(x) + (size_t)row0 * 32;
#pragma unroll
        for (int it = 0; it < 16; ++it) {
            int u = it * 256 + tid;
            int row = u >> 5, k4 = u & 31;
            float4 q = x4[row * 32 + k4];
            int tile = ((row >> 5) * 2) + ((row >> 4) & 1);
            int g = row & 7, h = (row >> 3) & 1;
            int ksv = k4 >> 1;
            int slot = ((k4 & 1) << 1) + h;
            int base = (((tile * 16 + ksv) * 32 + g * 4) << 2) + slot;
            float e[4] = {q.x, q.y, q.z, q.w};
#pragma unroll
            for (int j = 0; j < 4; ++j) {
                float hv = tf32r(e[j]);
                AH[base + j * 4] = hv;
                AL[base + j * 4] = tf32r(e[j] - hv);
            }
        }
    }

    const float4* cb4 = reinterpret_cast<const float4*>(cb);

    // ---- prefetch + store chunk 0 (raw floats, fragment-major) ----
    float4 pf[8];
#pragma unroll
    for (int it = 0; it < 8; ++it) {
        int u = it * 256 + tid;
        pf[it] = cb4[(size_t)(u >> 5) * 32 + (u & 31)];
    }
    {
        float* B = reinterpret_cast<float*>(smem + SM_B);
#pragma unroll
        for (int it = 0; it < 8; ++it) {
            int u = it * 256 + tid;
            int code = u >> 5, k4 = u & 31;
            int f = ((code >> 3) * 16 + (k4 >> 1)) * 64 + (code & 7) * 8 + (k4 & 1);
            B[f] = pf[it].x; B[f + 2] = pf[it].y;
            B[f + 4] = pf[it].z; B[f + 6] = pf[it].w;
        }
    }
    __syncthreads();

    float b1v[4], b2v[4];
    int   b1i[4], b2i[4];
#pragma unroll
    for (int i = 0; i < 4; ++i) { b1v[i] = 3.4e38f; b2v[i] = 3.4e38f;
                                  b1i[i] = 1 << 30; b2i[i] = 1 << 30; }

    for (int ch = 0; ch < CHUNKS; ++ch) {
        // prefetch next chunk into registers (hides LDG under mma)
        if (ch + 1 < CHUNKS) {
#pragma unroll
            for (int it = 0; it < 8; ++it) {
                int u = it * 256 + tid;
                pf[it] = cb4[((size_t)(ch + 1) * 64 + (u >> 5)) * 32 + (u & 31)];
            }
        }

        const char* Bb = smem + SM_B + (ch & 1) * 32768;
        float acc[2][4][4];
#pragma unroll
        for (int mt = 0; mt < 2; ++mt)
#pragma unroll
            for (int nt = 0; nt < 4; ++nt)
#pragma unroll
                for (int r = 0; r < 4; ++r) acc[mt][nt][r] = 0.0f;

#pragma unroll 2
        for (int ks = 0; ks < 16; ++ks) {
            uint4 ah0 = *reinterpret_cast<const uint4*>(
                smem + SM_AHI + ((rr * 2 + 0) * 16 + ks) * 512 + lane * 16);
            uint4 ah1 = *reinterpret_cast<const uint4*>(
                smem + SM_AHI + ((rr * 2 + 1) * 16 + ks) * 512 + lane * 16);
            uint4 al0 = *reinterpret_cast<const uint4*>(
                smem + SM_ALO + ((rr * 2 + 0) * 16 + ks) * 512 + lane * 16);
            uint4 al1 = *reinterpret_cast<const uint4*>(
                smem + SM_ALO + ((rr * 2 + 1) * 16 + ks) * 512 + lane * 16);
            uint32_t bh[4][2], bl[4][2];
#pragma unroll
            for (int nt = 0; nt < 4; ++nt) {
                float2 br = *reinterpret_cast<const float2*>(
                    Bb + ((cc * 4 + nt) * 16 + ks) * 256 + lane * 8);
                float h0 = tf32r(br.x), h1 = tf32r(br.y);
                bh[nt][0] = __float_as_uint(h0);
                bh[nt][1] = __float_as_uint(h1);
                bl[nt][0] = __float_as_uint(tf32r(br.x - h0));
                bl[nt][1] = __float_as_uint(tf32r(br.y - h1));
            }
#pragma unroll
            for (int nt = 0; nt < 4; ++nt) {
                mma8(acc[0][nt], reinterpret_cast<const uint32_t*>(&ah0), bh[nt]);
                mma8(acc[1][nt], reinterpret_cast<const uint32_t*>(&ah1), bh[nt]);
                mma8(acc[0][nt], reinterpret_cast<const uint32_t*>(&ah0), bl[nt]);
                mma8(acc[1][nt], reinterpret_cast<const uint32_t*>(&ah1), bl[nt]);
                mma8(acc[0][nt], reinterpret_cast<const uint32_t*>(&al0), bh[nt]);
                mma8(acc[1][nt], reinterpret_cast<const uint32_t*>(&al1), bh[nt]);
            }
        }

        // ---- epilogue: score = csq - 2*dot, per-row (best, second) ----
        int ib = (ch & 15) * 64;
#pragma unroll
        for (int nt = 0; nt < 4; ++nt) {
            int n0 = cc * 32 + nt * 8 + th * 2;
            float cs0 = __ldg(&g_csq[ch * 64 + n0]);
            float cs1 = __ldg(&g_csq[ch * 64 + n0 + 1]);
            int id0 = ib + n0, id1 = id0 + 1;
#pragma unroll
            for (int mt = 0; mt < 2; ++mt)
#pragma unroll
                for (int h = 0; h < 2; ++h) {
                    int rid = mt * 2 + h;
                    float s0 = fmaf(-2.0f, acc[mt][nt][h * 2],     cs0);
                    float s1 = fmaf(-2.0f, acc[mt][nt][h * 2 + 1], cs1);
                    upd(b1v[rid], b1i[rid], b2v[rid], b2i[rid], s0, id0);
                    upd(b1v[rid], b1i[rid], b2v[rid], b2i[rid], s1, id1);
                }
        }

        // ---- book end: reduce across lane quads, then across cc warps ----
        if ((ch & 15) == 15) {
            int book = ch >> 4;
#pragma unroll
            for (int rid = 0; rid < 4; ++rid) {
                float v1 = b1v[rid], v2 = b2v[rid];
                int   i1 = b1i[rid], i2 = b2i[rid];
#pragma unroll
                for (int off = 1; off < 4; off <<= 1) {
                    float ov1 = __shfl_xor_sync(0xffffffffu, v1, off);
                    int   oi1 = __shfl_xor_sync(0xffffffffu, i1, off);
                    float ov2 = __shfl_xor_sync(0xffffffffu, v2, off);
                    int   oi2 = __shfl_xor_sync(0xffffffffu, i2, off);
                    mrg(v1, i1, v2, i2, ov1, oi1, ov2, oi2);
                }
                b1v[rid] = v1; b1i[rid] = i1; b2v[rid] = v2; b2i[rid] = i2;
            }
            if (cc == 1 && th == 0) {
#pragma unroll
                for (int rid = 0; rid < 4; ++rid) {
                    int row = rr * 32 + (rid >> 1) * 16 + grp + (rid & 1) * 8;
                    EX[row] = make_float4(b1v[rid], __int_as_float(b1i[rid]),
                                          b2v[rid], __int_as_float(b2i[rid]));
                }
            }
            __syncthreads();
            if (cc == 0 && th == 0) {
#pragma unroll
                for (int rid = 0; rid < 4; ++rid) {
                    int row = rr * 32 + (rid >> 1) * 16 + grp + (rid & 1) * 8;
                    float4 o = EX[row];
                    float v1 = b1v[rid], v2 = b2v[rid];
                    int   i1 = b1i[rid], i2 = b2i[rid];
                    mrg(v1, i1, v2, i2, o.x, __float_as_int(o.y),
                        o.z, __float_as_int(o.w));
                    size_t oi = (size_t)(row0 + row) * NBOOK + book;
                    out[oi]    = (float)i1;
                    g_marg[oi] = v2 - v1;
                    g_sec[oi]  = i2;
                }
            }
#pragma unroll
            for (int i = 0; i < 4; ++i) { b1v[i] = 3.4e38f; b2v[i] = 3.4e38f;
                                          b1i[i] = 1 << 30; b2i[i] = 1 << 30; }
        }

        // ---- store next chunk's raw B frags ----
        if (ch + 1 < CHUNKS) {
            float* B = reinterpret_cast<float*>(smem + SM_B + ((ch + 1) & 1) * 32768);
#pragma unroll
            for (int it = 0; it < 8; ++it) {
                int u = it * 256 + tid;
                int code = u >> 5, k4 = u & 31;
                int f = ((code >> 3) * 16 + (k4 >> 1)) * 64 + (code & 7) * 8 + (k4 & 1);
                B[f] = pf[it].x; B[f + 2] = pf[it].y;
                B[f + 4] = pf[it].z; B[f + 6] = pf[it].w;
            }
        }
        __syncthreads();
    }
}

// Exact fp32 re-check for rows with small approx margin (guarantees 0 flips).
__global__ void recheck_kernel(const float* __restrict__ x,
                               const float* __restrict__ cb,
                               float* __restrict__ out) {
    int t = blockIdx.x * 256 + threadIdx.x;
    if (t >= NPTS * NBOOK) return;
    if (g_marg[t] >= 1e-3f) return;
    int row = t >> 2, book = t & 3;
    int i1 = (int)out[t];
    int i2 = g_sec[t];
    if (i2 >= KCODES) return;
    const float4* xr = reinterpret_cast<const float4*>(x) + (size_t)row * 32;
    const float4* c1 = reinterpret_cast<const float4*>(cb) +
                       ((size_t)book * KCODES + i1) * 32;
    const float4* c2 = reinterpret_cast<const float4*>(cb) +
                       ((size_t)book * KCODES + i2) * 32;
    float d1 = 0.f, d2 = 0.f;
#pragma unroll 8
    for (int k = 0; k < 32; ++k) {
        float4 a = xr[k], q1 = c1[k], q2 = c2[k];
        d1 = fmaf(a.x, q1.x, d1); d1 = fmaf(a.y, q1.y, d1);
        d1 = fmaf(a.z, q1.z, d1); d1 = fmaf(a.w, q1.w, d1);
        d2 = fmaf(a.x, q2.x, d2); d2 = fmaf(a.y, q2.y, d2);
        d2 = fmaf(a.z, q2.z, d2); d2 = fmaf(a.w, q2.w, d2);
    }
    float s1 = fmaf(-2.0f, d1, g_csq[book * KCODES + i1]);
    float s2 = fmaf(-2.0f, d2, g_csq[book * KCODES + i2]);
    out[t] = (float)(lless(s2, i2, s1, i1) ? i2 : i1);
}

extern "C" void kernel_launch(void* const* d_in, const int* in_sizes, int n_in,
                              void* d_out, int out_size) {
    const float* x  = nullptr;
    const float* cb = nullptr;
    for (int i = 0; i < n_in; ++i) {
        long long s = in_sizes[i];
        if (s == 16777216LL || s == 67108864LL) x  = (const float*)d_in[i];
        if (s == 524288LL   || s == 2097152LL)  cb = (const float*)d_in[i];
    }
    if (!x)  x  = (const float*)d_in[0];
    if (!cb) cb = (const float*)d_in[n_in > 1 ? 1 : 0];
    float* out = (float*)d_out;

    csq_kernel<<<NCODES / 8, 256>>>(cb);

    cudaFuncSetAttribute(rqk_mma, cudaFuncAttributeMaxDynamicSharedMemorySize,
                         SMEM_TOTAL);
    rqk_mma<<<NPTS / 128, THREADS, SMEM_TOTAL>>>(x, cb, out);

    recheck_kernel<<<(NPTS * NBOOK) / 256, 256>>>(x, cb, out);
}

// round 12
// speedup vs baseline: 1.2387x; 1.2387x over previous
#include <cuda_runtime.h>
#include <cstdint>

#define NPTS    131072
#define NBOOK   4
#define KCODES  1024
#define NCODES  4096
#define THREADS 256
#define CHUNK   32              // codes per chunk
#define CHUNKS  (NCODES / CHUNK)    // 128

// smem byte offsets
#define SM_AHI  0               // 64KB A-hi frags
#define SM_ALO  65536           // 64KB A-lo frags
#define SM_B    131072          // 2 x 32KB pre-split B frags (double buffer)
#define SM_EX   196608          // 2KB exchange
#define SMEM_TOTAL (196608 + 2048)

__device__ float  g_csq[NCODES];
__device__ float  g_marg[NPTS * NBOOK];
__device__ int    g_sec[NPTS * NBOOK];
// Pre-split B fragments: [chunk][n8grp(4)][ks(16)][lane(32)] = {b0h,b0l,b1h,b1l}
__device__ float4 g_bf[CHUNKS * 4 * 16 * 32];

__device__ __forceinline__ float tf32r(float v) {
    uint32_t r; asm("cvt.rna.tf32.f32 %0, %1;" : "=r"(r) : "f"(v));
    return __uint_as_float(r);
}
__device__ __forceinline__ bool lless(float v, int i, float v2, int i2) {
    return v < v2 || (v == v2 && i < i2);
}
__device__ __forceinline__ void upd(float& v1, int& i1, float& v2, int& i2,
                                    float s, int idx) {
    if (lless(s, idx, v1, i1)) { v2 = v1; i2 = i1; v1 = s; i1 = idx; }
    else if (lless(s, idx, v2, i2)) { v2 = s; i2 = idx; }
}
__device__ __forceinline__ void mrg(float& v1, int& i1, float& v2, int& i2,
                                    float ov1, int oi1, float ov2, int oi2) {
    if (lless(ov1, oi1, v1, i1)) {
        if (lless(v1, i1, ov2, oi2)) { v2 = v1; i2 = i1; }
        else { v2 = ov2; i2 = oi2; }
        v1 = ov1; i1 = oi1;
    } else if (lless(ov1, oi1, v2, i2)) { v2 = ov1; i2 = oi1; }
}
__device__ __forceinline__ void mma8(float* d, const uint32_t* a, const uint32_t* b) {
    asm volatile(
        "mma.sync.aligned.m16n8k8.row.col.f32.tf32.tf32.f32 "
        "{%0,%1,%2,%3}, {%4,%5,%6,%7}, {%8,%9}, {%0,%1,%2,%3};"
        : "+f"(d[0]), "+f"(d[1]), "+f"(d[2]), "+f"(d[3])
        : "r"(a[0]), "r"(a[1]), "r"(a[2]), "r"(a[3]), "r"(b[0]), "r"(b[1]));
}
__device__ __forceinline__ uint32_t smem_u32(const void* p) {
    return (uint32_t)__cvta_generic_to_shared(p);
}
__device__ __forceinline__ void cp16(uint32_t dst, const void* src) {
    asm volatile("cp.async.cg.shared.global [%0], [%1], 16;" :: "r"(dst), "l"(src));
}
__device__ __forceinline__ void cp_commit() { asm volatile("cp.async.commit_group;"); }
__device__ __forceinline__ void cp_wait()   { asm volatile("cp.async.wait_group 0;"); }

// ||c||^2 for all 4096 codes. One warp per code.
__global__ void csq_kernel(const float* __restrict__ cb) {
    int warp = threadIdx.x >> 5, lane = threadIdx.x & 31;
    int code = blockIdx.x * 8 + warp;
    float4 v = reinterpret_cast<const float4*>(cb)[code * 32 + lane];
    float s = v.x * v.x + v.y * v.y + v.z * v.z + v.w * v.w;
#pragma unroll
    for (int o = 16; o > 0; o >>= 1) s += __shfl_xor_sync(0xffffffffu, s, o);
    if (lane == 0) g_csq[code] = s;
}

// Pre-split B into tf32 hi/lo mma fragments (one float4 per lane-slot).
__global__ void bsplit_kernel(const float* __restrict__ cb) {
    int idx = blockIdx.x * 256 + threadIdx.x;      // 262144 total
    int lane = idx & 31;
    int ks   = (idx >> 5) & 15;
    int grp  = (idx >> 9) & 3;
    int chunk = idx >> 11;
    int code = chunk * CHUNK + grp * 8 + (lane >> 2);
    int k    = ks * 8 + (lane & 3);
    float b0 = cb[(size_t)code * 128 + k];
    float b1 = cb[(size_t)code * 128 + k + 4];
    float h0 = tf32r(b0), h1 = tf32r(b1);
    g_bf[idx] = make_float4(h0, tf32r(b0 - h0), h1, tf32r(b1 - h1));
}

extern __shared__ char smem[];

__global__ void __launch_bounds__(THREADS, 1)
rqk_mma(const float* __restrict__ x, float* __restrict__ out) {
    const int tid  = threadIdx.x;
    const int lane = tid & 31;
    const int warp = tid >> 5;
    const int rr   = warp & 3;     // rows rr*32..+31 (two m16 tiles)
    const int cc   = warp >> 2;    // codes cc*16..+15 of chunk (two n8 frags)
    const int grp  = lane >> 2;
    const int th   = lane & 3;
    const int row0 = blockIdx.x * 128;

    float*  AH = reinterpret_cast<float*>(smem + SM_AHI);
    float*  AL = reinterpret_cast<float*>(smem + SM_ALO);
    float4* EX = reinterpret_cast<float4*>(smem + SM_EX);

    // ---- A setup: load x rows, split tf32 hi/lo, store fragment-major ----
    {
        const float4* x4 = reinterpret_cast<const float4*>(x) + (size_t)row0 * 32;
#pragma unroll
        for (int it = 0; it < 16; ++it) {
            int u = it * 256 + tid;
            int row = u >> 5, k4 = u & 31;
            float4 q = x4[row * 32 + k4];
            int tile = ((row >> 5) * 2) + ((row >> 4) & 1);
            int g = row & 7, h = (row >> 3) & 1;
            int ksv = k4 >> 1;
            int slot = ((k4 & 1) << 1) + h;
            int base = (((tile * 16 + ksv) * 32 + g * 4) << 2) + slot;
            float e[4] = {q.x, q.y, q.z, q.w};
#pragma unroll
            for (int j = 0; j < 4; ++j) {
                float hv = tf32r(e[j]);
                AH[base + j * 4] = hv;
                AL[base + j * 4] = tf32r(e[j] - hv);
            }
        }
    }

    // ---- prefetch chunk 0 B frags (32KB contiguous) via cp.async ----
    {
        uint32_t dst = smem_u32(smem + SM_B);
        const float4* src = g_bf;
#pragma unroll
        for (int i = 0; i < 8; ++i)
            cp16(dst + (i * 256 + tid) * 16, src + i * 256 + tid);
        cp_commit();
    }
    cp_wait();
    __syncthreads();

    float b1v[4], b2v[4];
    int   b1i[4], b2i[4];
#pragma unroll
    for (int i = 0; i < 4; ++i) { b1v[i] = 3.4e38f; b2v[i] = 3.4e38f;
                                  b1i[i] = 1 << 30; b2i[i] = 1 << 30; }

    for (int ch = 0; ch < CHUNKS; ++ch) {
        // prefetch next chunk into the other buffer
        if (ch + 1 < CHUNKS) {
            uint32_t dst = smem_u32(smem + SM_B + ((ch + 1) & 1) * 32768);
            const float4* src = g_bf + (size_t)(ch + 1) * 2048;
#pragma unroll
            for (int i = 0; i < 8; ++i)
                cp16(dst + (i * 256 + tid) * 16, src + i * 256 + tid);
            cp_commit();
        }

        const char* Bb = smem + SM_B + (ch & 1) * 32768;
        float acc[2][2][4];
#pragma unroll
        for (int mt = 0; mt < 2; ++mt)
#pragma unroll
            for (int nt = 0; nt < 2; ++nt)
#pragma unroll
                for (int r = 0; r < 4; ++r) acc[mt][nt][r] = 0.0f;

#pragma unroll 4
        for (int ks = 0; ks < 16; ++ks) {
            uint4 ah0 = *reinterpret_cast<const uint4*>(
                smem + SM_AHI + ((rr * 2 + 0) * 16 + ks) * 512 + lane * 16);
            uint4 ah1 = *reinterpret_cast<const uint4*>(
                smem + SM_AHI + ((rr * 2 + 1) * 16 + ks) * 512 + lane * 16);
            uint4 al0 = *reinterpret_cast<const uint4*>(
                smem + SM_ALO + ((rr * 2 + 0) * 16 + ks) * 512 + lane * 16);
            uint4 al1 = *reinterpret_cast<const uint4*>(
                smem + SM_ALO + ((rr * 2 + 1) * 16 + ks) * 512 + lane * 16);
            // B frags: {b0h,b0l,b1h,b1l} per lane; grp index (cc*2+nt)
            float4 q0 = *reinterpret_cast<const float4*>(
                Bb + (((cc * 2 + 0) * 16 + ks) * 32 + lane) * 16);
            float4 q1 = *reinterpret_cast<const float4*>(
                Bb + (((cc * 2 + 1) * 16 + ks) * 32 + lane) * 16);
            uint32_t bh0[2] = {__float_as_uint(q0.x), __float_as_uint(q0.z)};
            uint32_t bl0[2] = {__float_as_uint(q0.y), __float_as_uint(q0.w)};
            uint32_t bh1[2] = {__float_as_uint(q1.x), __float_as_uint(q1.z)};
            uint32_t bl1[2] = {__float_as_uint(q1.y), __float_as_uint(q1.w)};
            const uint32_t* AH0 = reinterpret_cast<const uint32_t*>(&ah0);
            const uint32_t* AH1 = reinterpret_cast<const uint32_t*>(&ah1);
            const uint32_t* AL0 = reinterpret_cast<const uint32_t*>(&al0);
            const uint32_t* AL1 = reinterpret_cast<const uint32_t*>(&al1);
            // pass-major: accumulator reuse distance = 4 mma
            mma8(acc[0][0], AH0, bh0); mma8(acc[1][0], AH1, bh0);
            mma8(acc[0][1], AH0, bh1); mma8(acc[1][1], AH1, bh1);
            mma8(acc[0][0], AH0, bl0); mma8(acc[1][0], AH1, bl0);
            mma8(acc[0][1], AH0, bl1); mma8(acc[1][1], AH1, bl1);
            mma8(acc[0][0], AL0, bh0); mma8(acc[1][0], AL1, bh0);
            mma8(acc[0][1], AL0, bh1); mma8(acc[1][1], AL1, bh1);
        }

        // ---- epilogue: score = csq - 2*dot, per-row (best, second) ----
        int ib = (ch & 31) * CHUNK;
#pragma unroll
        for (int nt = 0; nt < 2; ++nt) {
            int n0 = cc * 16 + nt * 8 + th * 2;
            float cs0 = __ldg(&g_csq[ch * CHUNK + n0]);
            float cs1 = __ldg(&g_csq[ch * CHUNK + n0 + 1]);
            int id0 = ib + n0, id1 = id0 + 1;
#pragma unroll
            for (int mt = 0; mt < 2; ++mt)
#pragma unroll
                for (int h = 0; h < 2; ++h) {
                    int rid = mt * 2 + h;
                    float s0 = fmaf(-2.0f, acc[mt][nt][h * 2],     cs0);
                    float s1 = fmaf(-2.0f, acc[mt][nt][h * 2 + 1], cs1);
                    upd(b1v[rid], b1i[rid], b2v[rid], b2i[rid], s0, id0);
                    upd(b1v[rid], b1i[rid], b2v[rid], b2i[rid], s1, id1);
                }
        }

        // ---- book end: reduce lane quads, then across cc warps ----
        if ((ch & 31) == 31) {
            int book = ch >> 5;
#pragma unroll
            for (int rid = 0; rid < 4; ++rid) {
                float v1 = b1v[rid], v2 = b2v[rid];
                int   i1 = b1i[rid], i2 = b2i[rid];
#pragma unroll
                for (int off = 1; off < 4; off <<= 1) {
                    float ov1 = __shfl_xor_sync(0xffffffffu, v1, off);
                    int   oi1 = __shfl_xor_sync(0xffffffffu, i1, off);
                    float ov2 = __shfl_xor_sync(0xffffffffu, v2, off);
                    int   oi2 = __shfl_xor_sync(0xffffffffu, i2, off);
                    mrg(v1, i1, v2, i2, ov1, oi1, ov2, oi2);
                }
                b1v[rid] = v1; b1i[rid] = i1; b2v[rid] = v2; b2i[rid] = i2;
            }
            if (cc == 1 && th == 0) {
#pragma unroll
                for (int rid = 0; rid < 4; ++rid) {
                    int row = rr * 32 + (rid >> 1) * 16 + grp + (rid & 1) * 8;
                    EX[row] = make_float4(b1v[rid], __int_as_float(b1i[rid]),
                                          b2v[rid], __int_as_float(b2i[rid]));
                }
            }
            __syncthreads();
            if (cc == 0 && th == 0) {
#pragma unroll
                for (int rid = 0; rid < 4; ++rid) {
                    int row = rr * 32 + (rid >> 1) * 16 + grp + (rid & 1) * 8;
                    float4 o = EX[row];
                    float v1 = b1v[rid], v2 = b2v[rid];
                    int   i1 = b1i[rid], i2 = b2i[rid];
                    mrg(v1, i1, v2, i2, o.x, __float_as_int(o.y),
                        o.z, __float_as_int(o.w));
                    size_t oi = (size_t)(row0 + row) * NBOOK + book;
                    out[oi]    = (float)i1;
                    g_marg[oi] = v2 - v1;
                    g_sec[oi]  = i2;
                }
            }
#pragma unroll
            for (int i = 0; i < 4; ++i) { b1v[i] = 3.4e38f; b2v[i] = 3.4e38f;
                                          b1i[i] = 1 << 30; b2i[i] = 1 << 30; }
        }

        cp_wait();
        __syncthreads();   // next B buffer ready; all reads of current done
    }
}

// Exact fp32 re-check for rows with small approx margin (guarantees 0 flips).
__global__ void recheck_kernel(const float* __restrict__ x,
                               const float* __restrict__ cb,
                               float* __restrict__ out) {
    int t = blockIdx.x * 256 + threadIdx.x;
    if (t >= NPTS * NBOOK) return;
    if (g_marg[t] >= 1e-3f) return;
    int row = t >> 2, book = t & 3;
    int i1 = (int)out[t];
    int i2 = g_sec[t];
    if (i2 >= KCODES) return;
    const float4* xr = reinterpret_cast<const float4*>(x) + (size_t)row * 32;
    const float4* c1 = reinterpret_cast<const float4*>(cb) +
                       ((size_t)book * KCODES + i1) * 32;
    const float4* c2 = reinterpret_cast<const float4*>(cb) +
                       ((size_t)book * KCODES + i2) * 32;
    float d1 = 0.f, d2 = 0.f;
#pragma unroll 8
    for (int k = 0; k < 32; ++k) {
        float4 a = xr[k], q1 = c1[k], q2 = c2[k];
        d1 = fmaf(a.x, q1.x, d1); d1 = fmaf(a.y, q1.y, d1);
        d1 = fmaf(a.z, q1.z, d1); d1 = fmaf(a.w, q1.w, d1);
        d2 = fmaf(a.x, q2.x, d2); d2 = fmaf(a.y, q2.y, d2);
        d2 = fmaf(a.z, q2.z, d2); d2 = fmaf(a.w, q2.w, d2);
    }
    float s1 = fmaf(-2.0f, d1, g_csq[book * KCODES + i1]);
    float s2 = fmaf(-2.0f, d2, g_csq[book * KCODES + i2]);
    out[t] = (float)(lless(s2, i2, s1, i1) ? i2 : i1);
}

extern "C" void kernel_launch(void* const* d_in, const int* in_sizes, int n_in,
                              void* d_out, int out_size) {
    const float* x  = nullptr;
    const float* cb = nullptr;
    for (int i = 0; i < n_in; ++i) {
        long long s = in_sizes[i];
        if (s == 16777216LL || s == 67108864LL) x  = (const float*)d_in[i];
        if (s == 524288LL   || s == 2097152LL)  cb = (const float*)d_in[i];
    }
    if (!x)  x  = (const float*)d_in[0];
    if (!cb) cb = (const float*)d_in[n_in > 1 ? 1 : 0];
    float* out = (float*)d_out;

    csq_kernel<<<NCODES / 8, 256>>>(cb);
    bsplit_kernel<<<(CHUNKS * 4 * 16 * 32) / 256, 256>>>(cb);

    cudaFuncSetAttribute(rqk_mma, cudaFuncAttributeMaxDynamicSharedMemorySize,
                         SMEM_TOTAL);
    rqk_mma<<<NPTS / 128, THREADS, SMEM_TOTAL>>>(x, out);

    recheck_kernel<<<(NPTS * NBOOK) / 256, 256>>>(x, cb, out);
}

// round 13
// speedup vs baseline: 2.2817x; 1.8420x over previous
#include <cuda_runtime.h>
#include <cuda_fp16.h>
#include <cstdint>

#define NPTS    131072
#define NBOOK   4
#define KCODES  1024
#define NCODES  4096
#define THREADS 256
#define CHUNK   32
#define CHUNKS  (NCODES / CHUNK)    // 128

// smem byte offsets (total 98KB + 2KB)
#define SM_AH0  0               // 32KB A h0 frags
#define SM_AH1  32768           // 32KB A h1 frags
#define SM_B    65536           // 2 x 16KB pre-split B frags
#define SM_EX   98304           // 2KB exchange
#define SMEM_TOTAL (98304 + 2048)

__device__ float g_csq[NCODES];
__device__ float g_marg[NPTS * NBOOK];
// Pre-split B frags: [chunk(128)][n8grp(4)][ks(8)][lane(32)] -> {b0h0,b1h0,b0h1,b1h1} half2s
__device__ uint4 g_bf[CHUNKS * 4 * 8 * 32];

__device__ __forceinline__ bool lless(float v, int i, float v2, int i2) {
    return v < v2 || (v == v2 && i < i2);
}
__device__ __forceinline__ void upd(float& v1, int& i1, float& v2, int& i2,
                                    float s, int idx) {
    if (lless(s, idx, v1, i1)) { v2 = v1; i2 = i1; v1 = s; i1 = idx; }
    else if (lless(s, idx, v2, i2)) { v2 = s; i2 = idx; }
}
__device__ __forceinline__ void mrg(float& v1, int& i1, float& v2, int& i2,
                                    float ov1, int oi1, float ov2, int oi2) {
    if (lless(ov1, oi1, v1, i1)) {
        if (lless(v1, i1, ov2, oi2)) { v2 = v1; i2 = i1; }
        else { v2 = ov2; i2 = oi2; }
        v1 = ov1; i1 = oi1;
    } else if (lless(ov1, oi1, v2, i2)) { v2 = ov1; i2 = oi1; }
}
__device__ __forceinline__ void mma16(float* d, const uint32_t* a, const uint32_t* b) {
    asm volatile(
        "mma.sync.aligned.m16n8k16.row.col.f32.f16.f16.f32 "
        "{%0,%1,%2,%3}, {%4,%5,%6,%7}, {%8,%9}, {%0,%1,%2,%3};"
        : "+f"(d[0]), "+f"(d[1]), "+f"(d[2]), "+f"(d[3])
        : "r"(a[0]), "r"(a[1]), "r"(a[2]), "r"(a[3]), "r"(b[0]), "r"(b[1]));
}
__device__ __forceinline__ uint32_t smem_u32(const void* p) {
    return (uint32_t)__cvta_generic_to_shared(p);
}
__device__ __forceinline__ void cp16(uint32_t dst, const void* src) {
    asm volatile("cp.async.cg.shared.global [%0], [%1], 16;" :: "r"(dst), "l"(src));
}
__device__ __forceinline__ void cp_commit() { asm volatile("cp.async.commit_group;"); }
__device__ __forceinline__ void cp_wait()   { asm volatile("cp.async.wait_group 0;"); }
__device__ __forceinline__ uint32_t pack2(float a, float b) {
    __half2 h = __halves2half2(__float2half_rn(a), __float2half_rn(b));
    return *reinterpret_cast<uint32_t*>(&h);
}
__device__ __forceinline__ float lo_res(float v) {   // v - fp16(v)
    return v - __half2float(__float2half_rn(v));
}

// ||c||^2 for all 4096 codes. One warp per code.
__global__ void csq_kernel(const float* __restrict__ cb) {
    int warp = threadIdx.x >> 5, lane = threadIdx.x & 31;
    int code = blockIdx.x * 8 + warp;
    float4 v = reinterpret_cast<const float4*>(cb)[code * 32 + lane];
    float s = v.x * v.x + v.y * v.y + v.z * v.z + v.w * v.w;
#pragma unroll
    for (int o = 16; o > 0; o >>= 1) s += __shfl_xor_sync(0xffffffffu, s, o);
    if (lane == 0) g_csq[code] = s;
}

// Pre-split B into fp16 h0/h1 mma fragments.
__global__ void bsplit_kernel(const float* __restrict__ cb) {
    int idx = blockIdx.x * 256 + threadIdx.x;      // 131072 total
    int lane = idx & 31;
    int ks   = (idx >> 5) & 7;
    int grp  = (idx >> 8) & 3;
    int chunk = idx >> 10;
    int code = chunk * CHUNK + grp * 8 + (lane >> 2);
    const float* cr = cb + (size_t)code * 128 + ks * 16 + (lane & 3) * 2;
    float c0a = cr[0], c0b = cr[1], c1a = cr[8], c1b = cr[9];
    uint4 u;
    u.x = pack2(c0a, c0b);                    // b0 reg, h0 split
    u.y = pack2(c1a, c1b);                    // b1 reg, h0 split
    u.z = pack2(lo_res(c0a), lo_res(c0b));    // b0 reg, h1 split
    u.w = pack2(lo_res(c1a), lo_res(c1b));    // b1 reg, h1 split
    g_bf[idx] = u;
}

extern __shared__ char smem[];

__global__ void __launch_bounds__(THREADS, 2)
rqk_mma(const float* __restrict__ x, float* __restrict__ out) {
    const int tid  = threadIdx.x;
    const int lane = tid & 31;
    const int warp = tid >> 5;
    const int rr   = warp & 3;     // rows rr*32..+31 (two m16 tiles)
    const int cc   = warp >> 2;    // codes cc*16..+15 (two n8 frags)
    const int grp  = lane >> 2;
    const int th   = lane & 3;
    const int row0 = blockIdx.x * 128;

    float4* EX = reinterpret_cast<float4*>(smem + SM_EX);

    // ---- A setup: load rows, split fp16 h0/h1, store m16n8k16 frag-major ----
    {
        const float4* x4 = reinterpret_cast<const float4*>(x) + (size_t)row0 * 32;
#pragma unroll
        for (int it = 0; it < 16; ++it) {
            int u = it * 256 + tid;
            int row = u >> 5, k4 = u & 31;
            float4 q = x4[row * 32 + k4];
            int tile = row >> 4, r = row & 15;
            float e[4] = {q.x, q.y, q.z, q.w};
#pragma unroll
            for (int j = 0; j < 4; ++j) {
                int k = k4 * 4 + j;
                int ks = k >> 4, kk = k & 15;
                int reg = ((kk >> 3) << 1) | (r >> 3);
                int ln  = (r & 7) * 4 + ((kk & 7) >> 1);
                int off = (((tile * 8 + ks) * 32 + ln) << 4) + (reg << 2) + ((kk & 1) << 1);
                float hv = __half2float(__float2half_rn(e[j]));
                *reinterpret_cast<__half*>(smem + SM_AH0 + off) = __float2half_rn(e[j]);
                *reinterpret_cast<__half*>(smem + SM_AH1 + off) = __float2half_rn(e[j] - hv);
            }
        }
    }

    // ---- prefetch chunk 0 B frags (16KB) ----
    {
        uint32_t dst = smem_u32(smem + SM_B);
#pragma unroll
        for (int i = 0; i < 4; ++i)
            cp16(dst + (i * 256 + tid) * 16, g_bf + i * 256 + tid);
        cp_commit();
    }
    cp_wait();
    __syncthreads();

    float b1v[4], b2v[4];
    int   b1i[4], b2i[4];
#pragma unroll
    for (int i = 0; i < 4; ++i) { b1v[i] = 3.4e38f; b2v[i] = 3.4e38f;
                                  b1i[i] = 1 << 30; b2i[i] = 1 << 30; }

    for (int ch = 0; ch < CHUNKS; ++ch) {
        if (ch + 1 < CHUNKS) {
            uint32_t dst = smem_u32(smem + SM_B + ((ch + 1) & 1) * 16384);
            const uint4* src = g_bf + (size_t)(ch + 1) * 1024;
#pragma unroll
            for (int i = 0; i < 4; ++i)
                cp16(dst + (i * 256 + tid) * 16, src + i * 256 + tid);
            cp_commit();
        }

        const char* Bb = smem + SM_B + (ch & 1) * 16384;
        float acc[2][2][4];
#pragma unroll
        for (int mt = 0; mt < 2; ++mt)
#pragma unroll
            for (int nt = 0; nt < 2; ++nt)
#pragma unroll
                for (int r = 0; r < 4; ++r) acc[mt][nt][r] = 0.0f;

#pragma unroll
        for (int ks = 0; ks < 8; ++ks) {
            uint4 ah00 = *reinterpret_cast<const uint4*>(
                smem + SM_AH0 + (((rr * 2 + 0) * 8 + ks) * 32 + lane) * 16);
            uint4 ah01 = *reinterpret_cast<const uint4*>(
                smem + SM_AH0 + (((rr * 2 + 1) * 8 + ks) * 32 + lane) * 16);
            uint4 ah10 = *reinterpret_cast<const uint4*>(
                smem + SM_AH1 + (((rr * 2 + 0) * 8 + ks) * 32 + lane) * 16);
            uint4 ah11 = *reinterpret_cast<const uint4*>(
                smem + SM_AH1 + (((rr * 2 + 1) * 8 + ks) * 32 + lane) * 16);
            uint4 q0 = *reinterpret_cast<const uint4*>(
                Bb + (((cc * 2 + 0) * 8 + ks) * 32 + lane) * 16);
            uint4 q1 = *reinterpret_cast<const uint4*>(
                Bb + (((cc * 2 + 1) * 8 + ks) * 32 + lane) * 16);
            uint32_t bh0[2] = {q0.x, q0.y}, bl0[2] = {q0.z, q0.w};
            uint32_t bh1[2] = {q1.x, q1.y}, bl1[2] = {q1.z, q1.w};
            const uint32_t* A00 = reinterpret_cast<const uint32_t*>(&ah00);
            const uint32_t* A01 = reinterpret_cast<const uint32_t*>(&ah01);
            const uint32_t* A10 = reinterpret_cast<const uint32_t*>(&ah10);
            const uint32_t* A11 = reinterpret_cast<const uint32_t*>(&ah11);
            // products h0*h0, h0*h1, h1*h0 (pass-major, reuse distance 4)
            mma16(acc[0][0], A00, bh0); mma16(acc[1][0], A01, bh0);
            mma16(acc[0][1], A00, bh1); mma16(acc[1][1], A01, bh1);
            mma16(acc[0][0], A00, bl0); mma16(acc[1][0], A01, bl0);
            mma16(acc[0][1], A00, bl1); mma16(acc[1][1], A01, bl1);
            mma16(acc[0][0], A10, bh0); mma16(acc[1][0], A11, bh0);
            mma16(acc[0][1], A10, bh1); mma16(acc[1][1], A11, bh1);
        }

        // ---- epilogue: score = csq - 2*dot, per-row (best, second) ----
        int ib = (ch & 31) * CHUNK;
#pragma unroll
        for (int nt = 0; nt < 2; ++nt) {
            int n0 = cc * 16 + nt * 8 + th * 2;
            float cs0 = __ldg(&g_csq[ch * CHUNK + n0]);
            float cs1 = __ldg(&g_csq[ch * CHUNK + n0 + 1]);
            int id0 = ib + n0, id1 = id0 + 1;
#pragma unroll
            for (int mt = 0; mt < 2; ++mt)
#pragma unroll
                for (int h = 0; h < 2; ++h) {
                    int rid = mt * 2 + h;
                    float s0 = fmaf(-2.0f, acc[mt][nt][h * 2],     cs0);
                    float s1 = fmaf(-2.0f, acc[mt][nt][h * 2 + 1], cs1);
                    upd(b1v[rid], b1i[rid], b2v[rid], b2i[rid], s0, id0);
                    upd(b1v[rid], b1i[rid], b2v[rid], b2i[rid], s1, id1);
                }
        }

        // ---- book end: reduce lane quads, then across cc warps ----
        if ((ch & 31) == 31) {
            int book = ch >> 5;
#pragma unroll
            for (int rid = 0; rid < 4; ++rid) {
                float v1 = b1v[rid], v2 = b2v[rid];
                int   i1 = b1i[rid], i2 = b2i[rid];
#pragma unroll
                for (int off = 1; off < 4; off <<= 1) {
                    float ov1 = __shfl_xor_sync(0xffffffffu, v1, off);
                    int   oi1 = __shfl_xor_sync(0xffffffffu, i1, off);
                    float ov2 = __shfl_xor_sync(0xffffffffu, v2, off);
                    int   oi2 = __shfl_xor_sync(0xffffffffu, i2, off);
                    mrg(v1, i1, v2, i2, ov1, oi1, ov2, oi2);
                }
                b1v[rid] = v1; b1i[rid] = i1; b2v[rid] = v2; b2i[rid] = i2;
            }
            if (cc == 1 && th == 0) {
#pragma unroll
                for (int rid = 0; rid < 4; ++rid) {
                    int row = rr * 32 + (rid >> 1) * 16 + grp + (rid & 1) * 8;
                    EX[row] = make_float4(b1v[rid], __int_as_float(b1i[rid]),
                                          b2v[rid], __int_as_float(b2i[rid]));
                }
            }
            __syncthreads();
            if (cc == 0 && th == 0) {
#pragma unroll
                for (int rid = 0; rid < 4; ++rid) {
                    int row = rr * 32 + (rid >> 1) * 16 + grp + (rid & 1) * 8;
                    float4 o = EX[row];
                    float v1 = b1v[rid], v2 = b2v[rid];
                    int   i1 = b1i[rid], i2 = b2i[rid];
                    mrg(v1, i1, v2, i2, o.x, __float_as_int(o.y),
                        o.z, __float_as_int(o.w));
                    size_t oi = (size_t)(row0 + row) * NBOOK + book;
                    out[oi]    = (float)i1;
                    g_marg[oi] = v2 - v1;
                }
            }
#pragma unroll
            for (int i = 0; i < 4; ++i) { b1v[i] = 3.4e38f; b2v[i] = 3.4e38f;
                                          b1i[i] = 1 << 30; b2i[i] = 1 << 30; }
        }

        cp_wait();
        __syncthreads();
    }
}

// Full exact fp32 rescan for (row,book) pairs with small approx margin.
// Any possible argmin miss implies margin < 2*eps (eps <= ~3e-4), so
// threshold 2e-3 guarantees coverage. One warp per item; most exit early.
__global__ void recheck_kernel(const float* __restrict__ x,
                               const float* __restrict__ cb,
                               float* __restrict__ out) {
    int g = blockIdx.x * 256 + threadIdx.x;
    int w = g >> 5, lane = g & 31;
    if (w >= NPTS * NBOOK) return;
    if (g_marg[w] >= 2e-3f) return;
    int row = w >> 2, book = w & 3;
    const float4* xr = reinterpret_cast<const float4*>(x) + (size_t)row * 32;
    float bv = 3.4e38f; int bi = 1 << 30;
    for (int j = 0; j < 32; ++j) {
        int code = j * 32 + lane;
        const float4* cr = reinterpret_cast<const float4*>(cb) +
                           ((size_t)book * KCODES + code) * 32;
        float d = 0.0f;
#pragma unroll 8
        for (int k4 = 0; k4 < 32; ++k4) {
            float4 a = xr[k4], c = cr[k4];
            d = fmaf(a.x, c.x, d); d = fmaf(a.y, c.y, d);
            d = fmaf(a.z, c.z, d); d = fmaf(a.w, c.w, d);
        }
        float s = fmaf(-2.0f, d, g_csq[book * KCODES + code]);
        if (lless(s, code, bv, bi)) { bv = s; bi = code; }
    }
#pragma unroll
    for (int off = 16; off > 0; off >>= 1) {
        float ov = __shfl_xor_sync(0xffffffffu, bv, off);
        int   oi = __shfl_xor_sync(0xffffffffu, bi, off);
        if (lless(ov, oi, bv, bi)) { bv = ov; bi = oi; }
    }
    if (lane == 0) out[w] = (float)bi;
}

extern "C" void kernel_launch(void* const* d_in, const int* in_sizes, int n_in,
                              void* d_out, int out_size) {
    const float* x  = nullptr;
    const float* cb = nullptr;
    for (int i = 0; i < n_in; ++i) {
        long long s = in_sizes[i];
        if (s == 16777216LL || s == 67108864LL) x  = (const float*)d_in[i];
        if (s == 524288LL   || s == 2097152LL)  cb = (const float*)d_in[i];
    }
    if (!x)  x  = (const float*)d_in[0];
    if (!cb) cb = (const float*)d_in[n_in > 1 ? 1 : 0];
    float* out = (float*)d_out;

    csq_kernel<<<NCODES / 8, 256>>>(cb);
    bsplit_kernel<<<(CHUNKS * 4 * 8 * 32) / 256, 256>>>(cb);

    cudaFuncSetAttribute(rqk_mma, cudaFuncAttributeMaxDynamicSharedMemorySize,
                         SMEM_TOTAL);
    rqk_mma<<<NPTS / 128, THREADS, SMEM_TOTAL>>>(x, out);

    recheck_kernel<<<(NPTS * NBOOK * 32 + 255) / 256, 256>>>(x, cb, out);
}